// round 14
// baseline (speedup 1.0000x reference)
#include <cuda_runtime.h>
#include <math.h>

// Problem constants (fixed shapes)
namespace {
constexpr int Nn   = 65536;    // B*NPG nodes per side
constexpr int Cc   = 256;      // feature dim
constexpr int Ee   = 1048576;  // edges per edge set
constexpr int Bb   = 16;       // batch
constexpr int NPGv = 4096;     // nodes per graph
constexpr int Kk   = 1024;     // top-k
constexpr int NT   = 131072;   // 2*N
constexpr int PSPLIT = 16;     // pooling splits per (side,batch): 64 rows each
}

// Scratch (device globals: no allocation allowed)
__device__ float2 g_kv[NT];    // (k, v) packed -> one gather sector
__device__ float  g_q[NT];     // compact q table (L1 evict_last gathers)
__device__ float2 g_dn[NT];    // (num, den) atomic accumulators
__device__ int    g_sel[2 * Bb * Kk];   // compacted selected row indices (local)
__device__ float  g_selw[2 * Bb * Kk];  // matching weights tanh(score)/K

// ---- float <-> order-preserving uint ------------------------------------
__device__ __forceinline__ unsigned encf(float f) {
    unsigned u = __float_as_uint(f);
    return (u & 0x80000000u) ? ~u : (u | 0x80000000u);
}

// q gather: pin in L1 (high reuse)
__device__ __forceinline__ float ldg_evict_last(const float* p) {
    float v;
    asm("ld.global.nc.L1::evict_last.f32 %0, [%1];" : "=f"(v) : "l"(p));
    return v;
}
// kv gather: don't displace the pinned q lines
__device__ __forceinline__ float2 ldg_kv_evict_first(const float2* p) {
    float2 v;
    asm("ld.global.nc.L1::evict_first.v2.f32 {%0, %1}, [%2];"
        : "=f"(v.x), "=f"(v.y) : "l"(p));
    return v;
}

// ---- kqv (one side per launch): 4 nodes per warp, 8 loads in flight -------
// Also zeroes g_dn for its own nodes.
__global__ void __launch_bounds__(512)
kqv_kernel(const float* __restrict__ x, const float* __restrict__ w,
           const float* __restrict__ bb, int node_off) {
    __shared__ float4 sw0[Cc / 4], sw1[Cc / 4], sw2[Cc / 4];
    __shared__ float  sb[3];
    for (int c = threadIdx.x; c < Cc; c += blockDim.x) {
        reinterpret_cast<float*>(sw0)[c] = w[c * 3 + 0];
        reinterpret_cast<float*>(sw1)[c] = w[c * 3 + 1];
        reinterpret_cast<float*>(sw2)[c] = w[c * 3 + 2];
    }
    if (threadIdx.x < 3) sb[threadIdx.x] = bb[threadIdx.x];
    __syncthreads();

    int warp = threadIdx.x >> 5;
    int lane = threadIdx.x & 31;
    float4 rw0[2] = {sw0[lane], sw0[lane + 32]};
    float4 rw1[2] = {sw1[lane], sw1[lane + 32]};
    float4 rw2[2] = {sw2[lane], sw2[lane + 32]};

    int local = blockIdx.x * 64 + warp * 4;     // local node base within side
    const float* xr = x + (long long)local * Cc;

    // issue all 8 independent loads first (MLP=8)
    float4 xv[4][2];
#pragma unroll
    for (int n = 0; n < 4; ++n)
#pragma unroll
        for (int h = 0; h < 2; ++h)
            xv[n][h] = __ldcs(reinterpret_cast<const float4*>(xr + n * Cc + (lane + h * 32) * 4));

    float s[4][3];
#pragma unroll
    for (int n = 0; n < 4; ++n) {
        float s0 = 0.f, s1 = 0.f, s2 = 0.f;
#pragma unroll
        for (int h = 0; h < 2; ++h) {
            float4 v  = xv[n][h];
            float4 w0 = rw0[h], w1 = rw1[h], w2 = rw2[h];
            s0 += v.x * w0.x + v.y * w0.y + v.z * w0.z + v.w * w0.w;
            s1 += v.x * w1.x + v.y * w1.y + v.z * w1.z + v.w * w1.w;
            s2 += v.x * w2.x + v.y * w2.y + v.z * w2.z + v.w * w2.w;
        }
        s[n][0] = s0; s[n][1] = s1; s[n][2] = s2;
    }

    // folded multi-node reduction: 27 shuffles for 4 nodes x 3 channels
    float e[3];
#pragma unroll
    for (int v = 0; v < 3; ++v) {
        float t0 = __shfl_xor_sync(0xFFFFFFFFu, s[0][v], 16);
        float t1 = __shfl_xor_sync(0xFFFFFFFFu, s[1][v], 16);
        float c01 = (lane & 16) ? (s[1][v] + t1) : (s[0][v] + t0);
        float t2 = __shfl_xor_sync(0xFFFFFFFFu, s[2][v], 16);
        float t3 = __shfl_xor_sync(0xFFFFFFFFu, s[3][v], 16);
        float c23 = (lane & 16) ? (s[3][v] + t3) : (s[2][v] + t2);
        float u01 = __shfl_xor_sync(0xFFFFFFFFu, c01, 8);
        float u23 = __shfl_xor_sync(0xFFFFFFFFu, c23, 8);
        float ev = (lane & 8) ? (c23 + u23) : (c01 + u01);
        ev += __shfl_xor_sync(0xFFFFFFFFu, ev, 4);
        ev += __shfl_xor_sync(0xFFFFFFFFu, ev, 2);
        ev += __shfl_xor_sync(0xFFFFFFFFu, ev, 1);
        e[v] = ev;
    }
    // lanes 0,8,16,24 hold nodes 0,2,1,3 respectively
    if ((lane & 7) == 0) {
        int n = ((lane >> 4) & 1) + ((lane >> 3) & 1) * 2;
        int node = node_off + local + n;
        g_kv[node] = make_float2(e[0] + sb[0], e[2] + sb[2]);   // (k, v)
        g_q[node]  = e[1] + sb[1];
        g_dn[node] = make_float2(0.f, 0.f);
    }
}

// shared 8-edge body
__device__ __forceinline__ void edge_body8(
    int4 ss0, int4 ss1, int4 dd0, int4 dd1, int sbase, int dbase,
    float kw, float kb, float vw, float vb, float pr) {
    int s[8] = {ss0.x, ss0.y, ss0.z, ss0.w, ss1.x, ss1.y, ss1.z, ss1.w};
    int d[8] = {dd0.x, dd0.y, dd0.z, dd0.w, dd1.x, dd1.y, dd1.z, dd1.w};
    float2 kv[8];
    float  q[8];
#pragma unroll
    for (int u = 0; u < 8; ++u) kv[u] = ldg_kv_evict_first(&g_kv[sbase + s[u]]);
#pragma unroll
    for (int u = 0; u < 8; ++u) q[u]  = ldg_evict_last(&g_q[dbase + d[u]]);
#pragma unroll
    for (int u = 0; u < 8; ++u) {
        float ex = __expf(q[u] * (kv[u].x * kw + kb) * pr);
        float ve = kv[u].y * vw + vb;
        atomicAdd(&g_dn[dbase + d[u]], make_float2(ex * ve, ex));
    }
}

// ---- edge t=2 (i2i): depends ONLY on kqv_inst; overlaps kqv_data ----------
__global__ void __launch_bounds__(512)
edge2_kernel(const int* __restrict__ ei2,
             const float* __restrict__ krel_w, const float* __restrict__ krel_b,
             const float* __restrict__ vrel_w, const float* __restrict__ vrel_b,
             const float* __restrict__ p_rel) {
    int gi = (blockIdx.x << 9) | threadIdx.x;                  // 0..Ee/8-1
    const int4* sp = reinterpret_cast<const int4*>(ei2) + gi * 2;
    const int4* dp = reinterpret_cast<const int4*>(ei2 + Ee) + gi * 2;
    int4 ss0 = __ldcs(sp), ss1 = __ldcs(sp + 1);
    int4 dd0 = __ldcs(dp), dd1 = __ldcs(dp + 1);
    float kw = krel_w[2], kb = krel_b[2];
    float vw = vrel_w[2], vb = vrel_b[2];
    float pr = p_rel[2];
    cudaGridDependencySynchronize();                           // kqv_inst done
    edge_body8(ss0, ss1, dd0, dd1, /*sbase=*/0, /*dbase=*/0, kw, kb, vw, vb, pr);
}

// ---- edge t=0,1 interleaved: needs both sides ------------------------------
__global__ void __launch_bounds__(512)
edge01_kernel(const int* __restrict__ ei0, const int* __restrict__ ei1,
              const float* __restrict__ krel_w, const float* __restrict__ krel_b,
              const float* __restrict__ vrel_w, const float* __restrict__ vrel_b,
              const float* __restrict__ p_rel) {
    int t  = blockIdx.x & 1;                                   // 0 or 1
    int gi = ((blockIdx.x >> 1) << 9) | threadIdx.x;           // 0..Ee/8-1
    const int* ei = (t == 0) ? ei0 : ei1;
    const int4* sp = reinterpret_cast<const int4*>(ei) + gi * 2;
    const int4* dp = reinterpret_cast<const int4*>(ei + Ee) + gi * 2;
    int4 ss0 = __ldcs(sp), ss1 = __ldcs(sp + 1);
    int4 dd0 = __ldcs(dp), dd1 = __ldcs(dp + 1);
    float kw = krel_w[t], kb = krel_b[t];
    float vw = vrel_w[t], vb = vrel_b[t];
    float pr = p_rel[t];
    cudaGridDependencySynchronize();   // transitively: both kqv sides + edge2
    int sbase = (t == 1) ? Nn : 0;
    int dbase = (t == 0) ? Nn : 0;
    edge_body8(ss0, ss1, dd0, dd1, sbase, dbase, kw, kb, vw, vb, pr);
}

// ---- score + per-batch top-K (radix select) + compaction -------------------
__global__ void __launch_bounds__(1024)
select_kernel(const float* __restrict__ w_out_i, const float* __restrict__ b_out_i,
              const float* __restrict__ w_out_d, const float* __restrict__ b_out_d,
              float* __restrict__ out) {
    constexpr int T = 1024;
    constexpr int CHUNK = NPGv / T;   // 4
    __shared__ unsigned skey[NPGv];
    __shared__ float    sval[NPGv];
    __shared__ int      hist[256];
    __shared__ int      s_sel, s_rem;
    __shared__ int      warp_sums[32];
    int tid  = threadIdx.x;
    int side = blockIdx.x >> 4;      // 0..1
    int b    = blockIdx.x & 15;      // 0..15
    int base = side * Nn + b * NPGv;
    int obase = (side * Bb + b) * Kk;
    float wo = side ? w_out_d[0] : w_out_i[0];
    float bo = side ? b_out_d[0] : b_out_i[0];

    if (tid < Cc) out[b * (2 * Cc) + side * Cc + tid] = 0.f;   // zero own out slice

    cudaGridDependencySynchronize();   // g_dn ready

    for (int j = tid; j < NPGv; j += T) {
        float2 dn = g_dn[base + j];
        float a   = (dn.y > 0.f) ? (dn.x / dn.y) : 0.f;   // empty segment -> 0
        float z   = a * wo + bo;
        float sc  = 0.5f * z * (1.f + erff(z * 0.70710678118654752f));  // exact gelu
        sval[j] = sc;
        skey[j] = encf(sc);
    }
    if (tid == 0) s_rem = Kk;

    // 4-pass radix select for the Kk-th largest key
    unsigned prefix = 0u;
#pragma unroll
    for (int shift = 24; shift >= 0; shift -= 8) {
        unsigned umask = (shift == 24) ? 0u : (0xFFFFFFFFu << (shift + 8));
        __syncthreads();
        if (tid < 256) hist[tid] = 0;
        __syncthreads();
#pragma unroll
        for (int u = 0; u < CHUNK; ++u) {
            unsigned key = skey[tid + u * T];
            bool act = (key & umask) == (prefix & umask);
            if (act) {
                unsigned bin   = (key >> shift) & 255u;
                unsigned peers = __match_any_sync(__activemask(), bin);
                int leader = __ffs(peers) - 1;
                if ((tid & 31) == leader) atomicAdd(&hist[bin], __popc(peers));
            }
        }
        __syncthreads();
        if (tid < 32) {
            int rem = s_rem;
            int h[8], sfx[8];
            int bin0 = tid * 8;
#pragma unroll
            for (int j = 0; j < 8; ++j) h[j] = hist[bin0 + j];
            sfx[7] = h[7];
#pragma unroll
            for (int j = 6; j >= 0; --j) sfx[j] = h[j] + sfx[j + 1];
            int tot = sfx[0];
            int suf = tot;
#pragma unroll
            for (int off = 1; off < 32; off <<= 1) {
                int v = __shfl_down_sync(0xFFFFFFFFu, suf, off);
                if (tid + off < 32) suf += v;
            }
            int above_lane = suf - tot;   // sum of bins >= (tid+1)*8
#pragma unroll
            for (int j = 0; j < 8; ++j) {
                int cnt_ge    = sfx[j] + above_lane;
                int cnt_above = (j == 7) ? above_lane : (sfx[j + 1] + above_lane);
                if (cnt_ge >= rem && cnt_above < rem) {
                    s_sel = bin0 + j;
                    s_rem = rem - cnt_above;
                }
            }
        }
        __syncthreads();
        prefix |= ((unsigned)s_sel) << shift;
    }
    unsigned thr = prefix;           // Kk-th largest key
    int need_eq = s_rem;             // #ties at thr to keep (lowest index first)

    int lane = tid & 31, warp = tid >> 5;
    auto excl_scan = [&](int cnt) -> int {
        int incl = cnt;
#pragma unroll
        for (int off = 1; off < 32; off <<= 1) {
            int v = __shfl_up_sync(0xFFFFFFFFu, incl, off);
            if (lane >= off) incl += v;
        }
        if (lane == 31) warp_sums[warp] = incl;
        __syncthreads();
        if (tid < 32) {
            int v = warp_sums[tid];
#pragma unroll
            for (int off = 1; off < 32; off <<= 1) {
                int t2 = __shfl_up_sync(0xFFFFFFFFu, v, off);
                if (tid >= off) v += t2;
            }
            warp_sums[tid] = v;
        }
        __syncthreads();
        return incl - cnt + (warp ? warp_sums[warp - 1] : 0);
    };

    // tie-rank scan (ascending index over keys == thr)
    int j0 = tid * CHUNK;
    int myties = 0;
#pragma unroll
    for (int u = 0; u < CHUNK; ++u) myties += (skey[j0 + u] == thr) ? 1 : 0;
    int r = excl_scan(myties);

    unsigned selmask = 0u;
    int nsel = 0;
#pragma unroll
    for (int u = 0; u < CHUNK; ++u) {
        unsigned key = skey[j0 + u];
        bool sel = key > thr;
        if (key == thr) { sel = (r < need_eq); ++r; }
        if (sel) { selmask |= (1u << u); ++nsel; }
    }
    __syncthreads();                 // warp_sums reuse
    int pos = excl_scan(nsel);

#pragma unroll
    for (int u = 0; u < CHUNK; ++u) {
        if (selmask & (1u << u)) {
            int j = j0 + u;
            g_sel[obase + pos]  = j;
            g_selw[obase + pos] = tanhf(sval[j]) * (1.f / (float)Kk);
            ++pos;
        }
    }
}

// ---- pooling: dense weighted sum over compacted top-K rows -----------------
__global__ void __launch_bounds__(256)
pool_kernel(const float* __restrict__ x_i, const float* __restrict__ x_d,
            float* __restrict__ out) {
    constexpr int RPB = Kk / PSPLIT;     // 64 rows per block
    __shared__ int   sidx[RPB];
    __shared__ float swt[RPB];
    int part = blockIdx.x & (PSPLIT - 1);
    int sb   = blockIdx.x >> 4;          // PSPLIT == 16
    int side = sb >> 4;
    int b    = sb & 15;
    const float* x = side ? x_d : x_i;
    int obase = (side * Bb + b) * Kk + part * RPB;
    long long xgbase = (long long)b * NPGv * Cc;

    cudaGridDependencySynchronize();     // g_sel/g_selw + out-zero ready

    if (threadIdx.x < RPB) {
        sidx[threadIdx.x] = g_sel[obase + threadIdx.x];
        swt[threadIdx.x]  = g_selw[obase + threadIdx.x];
    }
    __syncthreads();

    int cg = threadIdx.x & 63;           // float4 column group
    int rg = threadIdx.x >> 6;           // row group 0..3
    float4 acc = make_float4(0.f, 0.f, 0.f, 0.f);
#pragma unroll 16
    for (int r = rg; r < RPB; r += 4) {
        int   row = sidx[r];
        float w   = swt[r];
        float4 xv = __ldg(reinterpret_cast<const float4*>(x + xgbase + (long long)row * Cc + cg * 4));
        acc.x += w * xv.x; acc.y += w * xv.y;
        acc.z += w * xv.z; acc.w += w * xv.w;
    }
    float* o = &out[b * (2 * Cc) + side * Cc + cg * 4];
    atomicAdd(reinterpret_cast<float2*>(o),     make_float2(acc.x, acc.y));
    atomicAdd(reinterpret_cast<float2*>(o + 2), make_float2(acc.z, acc.w));
}

// ---- launch ----------------------------------------------------------------
extern "C" void kernel_launch(void* const* d_in, const int* in_sizes, int n_in,
                              void* d_out, int out_size) {
    const float* x_inst     = (const float*)d_in[0];
    const float* x_data     = (const float*)d_in[1];
    const float* w_kqv_inst = (const float*)d_in[2];
    const float* b_kqv_inst = (const float*)d_in[3];
    const float* w_kqv_data = (const float*)d_in[4];
    const float* b_kqv_data = (const float*)d_in[5];
    const float* w_out_inst = (const float*)d_in[6];
    const float* b_out_inst = (const float*)d_in[7];
    const float* w_out_data = (const float*)d_in[8];
    const float* b_out_data = (const float*)d_in[9];
    const float* krel_w     = (const float*)d_in[10];
    const float* krel_b     = (const float*)d_in[11];
    const float* vrel_w     = (const float*)d_in[12];
    const float* vrel_b     = (const float*)d_in[13];
    const float* p_rel      = (const float*)d_in[14];
    const int*   ei_i2d     = (const int*)d_in[15];
    const int*   ei_d2i     = (const int*)d_in[16];
    const int*   ei_i2i     = (const int*)d_in[17];
    float* out = (float*)d_out;

    cudaLaunchAttribute attr[1];
    attr[0].id = cudaLaunchAttributeProgrammaticStreamSerialization;
    attr[0].val.programmaticStreamSerializationAllowed = 1;

    // 1) inst-side kqv
    kqv_kernel<<<Nn / 64, 512>>>(x_inst, w_kqv_inst, b_kqv_inst, 0);

    // 2) edge t=2 (i2i): syncs on kqv_inst only
    {
        cudaLaunchConfig_t cfg = {};
        cfg.gridDim  = dim3(Ee / 4096);
        cfg.blockDim = dim3(512);
        cfg.attrs = attr; cfg.numAttrs = 1;
        cudaLaunchKernelEx(&cfg, edge2_kernel, ei_i2i,
                           krel_w, krel_b, vrel_w, vrel_b, p_rel);
    }
    // 3) data-side kqv: NO grid sync inside -> overlaps edge2 fully
    {
        cudaLaunchConfig_t cfg = {};
        cfg.gridDim  = dim3(Nn / 64);
        cfg.blockDim = dim3(512);
        cfg.attrs = attr; cfg.numAttrs = 1;
        cudaLaunchKernelEx(&cfg, kqv_kernel, x_data, w_kqv_data, b_kqv_data, (int)Nn);
    }
    // 4) edge t=0,1: syncs (transitively) on everything above
    {
        cudaLaunchConfig_t cfg = {};
        cfg.gridDim  = dim3(2 * (Ee / 4096));
        cfg.blockDim = dim3(512);
        cfg.attrs = attr; cfg.numAttrs = 1;
        cudaLaunchKernelEx(&cfg, edge01_kernel, ei_i2d, ei_d2i,
                           krel_w, krel_b, vrel_w, vrel_b, p_rel);
    }
    // 5) select
    {
        cudaLaunchConfig_t cfg = {};
        cfg.gridDim  = dim3(2 * Bb);
        cfg.blockDim = dim3(1024);
        cfg.attrs = attr; cfg.numAttrs = 1;
        cudaLaunchKernelEx(&cfg, select_kernel, w_out_inst, b_out_inst,
                           w_out_data, b_out_data, out);
    }
    // 6) pool
    {
        cudaLaunchConfig_t cfg = {};
        cfg.gridDim  = dim3(2 * Bb * PSPLIT);
        cfg.blockDim = dim3(256);
        cfg.attrs = attr; cfg.numAttrs = 1;
        cudaLaunchKernelEx(&cfg, pool_kernel, x_inst, x_data, out);
    }
}

// round 15
// speedup vs baseline: 1.0116x; 1.0116x over previous
#include <cuda_runtime.h>
#include <math.h>

// Problem constants (fixed shapes)
namespace {
constexpr int Nn   = 65536;    // B*NPG nodes per side
constexpr int Cc   = 256;      // feature dim
constexpr int Ee   = 1048576;  // edges per edge set
constexpr int Bb   = 16;       // batch
constexpr int NPGv = 4096;     // nodes per graph
constexpr int Kk   = 1024;     // top-k
constexpr int NT   = 131072;   // 2*N
constexpr int PSPLIT = 16;     // pooling splits per (side,batch): 64 rows each
}

// Scratch (device globals: no allocation allowed)
__device__ float2 g_kv[NT];    // (k, v) packed -> one gather sector
__device__ float  g_q[NT];     // compact q table (L1 evict_last gathers)
__device__ float2 g_dn[NT];    // (num, den) atomic accumulators
__device__ int    g_sel[2 * Bb * Kk];   // compacted selected row indices (local)
__device__ float  g_selw[2 * Bb * Kk];  // matching weights tanh(score)/K

// ---- float <-> order-preserving uint ------------------------------------
__device__ __forceinline__ unsigned encf(float f) {
    unsigned u = __float_as_uint(f);
    return (u & 0x80000000u) ? ~u : (u | 0x80000000u);
}

// q gather: pin in L1 (high reuse)
__device__ __forceinline__ float ldg_evict_last(const float* p) {
    float v;
    asm("ld.global.nc.L1::evict_last.f32 %0, [%1];" : "=f"(v) : "l"(p));
    return v;
}
// kv gather: don't displace the pinned q lines
__device__ __forceinline__ float2 ldg_kv_evict_first(const float2* p) {
    float2 v;
    asm("ld.global.nc.L1::evict_first.v2.f32 {%0, %1}, [%2];"
        : "=f"(v.x), "=f"(v.y) : "l"(p));
    return v;
}

// ---- kqv: 4 nodes per warp, 8 loads in flight, register weights -----------
// Also zeroes g_dn (runs before edge_kernel). Default cache policy on x so
// the stream populates L2 for pool_kernel's re-reads (L2 = 126MB ~ |x|).
__global__ void __launch_bounds__(512)
kqv_kernel(const float* __restrict__ x_i, const float* __restrict__ x_d,
           const float* __restrict__ w_i, const float* __restrict__ b_i,
           const float* __restrict__ w_d, const float* __restrict__ b_d) {
    __shared__ float4 sw0[Cc / 4], sw1[Cc / 4], sw2[Cc / 4];
    __shared__ float  sb[3];
    int node0 = blockIdx.x * 64;         // 16 warps x 4 nodes per block
    int side  = (node0 >= Nn) ? 1 : 0;   // Nn % 64 == 0 -> block never straddles
    const float* w  = side ? w_d : w_i;
    const float* bb = side ? b_d : b_i;
    for (int c = threadIdx.x; c < Cc; c += blockDim.x) {
        reinterpret_cast<float*>(sw0)[c] = w[c * 3 + 0];
        reinterpret_cast<float*>(sw1)[c] = w[c * 3 + 1];
        reinterpret_cast<float*>(sw2)[c] = w[c * 3 + 2];
    }
    if (threadIdx.x < 3) sb[threadIdx.x] = bb[threadIdx.x];
    __syncthreads();

    int warp = threadIdx.x >> 5;
    int lane = threadIdx.x & 31;
    float4 rw0[2] = {sw0[lane], sw0[lane + 32]};
    float4 rw1[2] = {sw1[lane], sw1[lane + 32]};
    float4 rw2[2] = {sw2[lane], sw2[lane + 32]};

    int nbase = node0 + warp * 4;
    const float* x = side ? (x_d + (long long)(nbase - Nn) * Cc)
                          : (x_i + (long long)nbase * Cc);

    // issue all 8 independent loads first (MLP=8); default policy -> L2 fill
    float4 xv[4][2];
#pragma unroll
    for (int n = 0; n < 4; ++n)
#pragma unroll
        for (int h = 0; h < 2; ++h)
            xv[n][h] = *reinterpret_cast<const float4*>(x + n * Cc + (lane + h * 32) * 4);

#pragma unroll
    for (int n = 0; n < 4; ++n) {
        float s0 = 0.f, s1 = 0.f, s2 = 0.f;
#pragma unroll
        for (int h = 0; h < 2; ++h) {
            float4 v  = xv[n][h];
            float4 w0 = rw0[h], w1 = rw1[h], w2 = rw2[h];
            s0 += v.x * w0.x + v.y * w0.y + v.z * w0.z + v.w * w0.w;
            s1 += v.x * w1.x + v.y * w1.y + v.z * w1.z + v.w * w1.w;
            s2 += v.x * w2.x + v.y * w2.y + v.z * w2.z + v.w * w2.w;
        }
#pragma unroll
        for (int o = 16; o; o >>= 1) {
            s0 += __shfl_down_sync(0xFFFFFFFFu, s0, o);
            s1 += __shfl_down_sync(0xFFFFFFFFu, s1, o);
            s2 += __shfl_down_sync(0xFFFFFFFFu, s2, o);
        }
        if (lane == 0) {
            int node = nbase + n;
            g_kv[node] = make_float2(s0 + sb[0], s2 + sb[2]);   // (k, v)
            g_q[node]  = s1 + sb[1];
            g_dn[node] = make_float2(0.f, 0.f);
        }
    }
}

// ---- single fused edge pass: 8 edges/thread, exp sums, no max-shift --------
// PDL: index loads (pure inputs) issue BEFORE the grid dependency sync.
__global__ void __launch_bounds__(512)
edge_kernel(const int* __restrict__ ei0, const int* __restrict__ ei1,
            const int* __restrict__ ei2,
            const float* __restrict__ krel_w, const float* __restrict__ krel_b,
            const float* __restrict__ vrel_w, const float* __restrict__ vrel_b,
            const float* __restrict__ p_rel) {
    int t  = blockIdx.x >> 8;                                  // 0,1,2 (uniform per block)
    int gi = ((blockIdx.x & 255) << 9) | threadIdx.x;          // 8-edge group, 0..Ee/8-1
    const int* ei = (t == 0) ? ei0 : ((t == 1) ? ei1 : ei2);
    const int4* sp = reinterpret_cast<const int4*>(ei) + gi * 2;
    const int4* dp = reinterpret_cast<const int4*>(ei + Ee) + gi * 2;
    int4 ss0 = __ldcs(sp), ss1 = __ldcs(sp + 1);
    int4 dd0 = __ldcs(dp), dd1 = __ldcs(dp + 1);
    float kw = krel_w[t], kb = krel_b[t];
    float vw = vrel_w[t], vb = vrel_b[t];
    float pr = p_rel[t];

    cudaGridDependencySynchronize();   // now g_kv/g_q/g_dn are ready

    int sbase = (t == 1) ? Nn : 0;
    int dbase = (t == 0) ? Nn : 0;
    int s[8] = {ss0.x, ss0.y, ss0.z, ss0.w, ss1.x, ss1.y, ss1.z, ss1.w};
    int d[8] = {dd0.x, dd0.y, dd0.z, dd0.w, dd1.x, dd1.y, dd1.z, dd1.w};
    float2 kv[8];
    float  q[8];
#pragma unroll
    for (int u = 0; u < 8; ++u) kv[u] = ldg_kv_evict_first(&g_kv[sbase + s[u]]);
#pragma unroll
    for (int u = 0; u < 8; ++u) q[u]  = ldg_evict_last(&g_q[dbase + d[u]]);
#pragma unroll
    for (int u = 0; u < 8; ++u) {
        float ex = __expf(q[u] * (kv[u].x * kw + kb) * pr);
        float ve = kv[u].y * vw + vb;
        atomicAdd(&g_dn[dbase + d[u]], make_float2(ex * ve, ex));
    }
}

// ---- score + per-batch top-K (radix select) + compaction -------------------
__global__ void __launch_bounds__(1024)
select_kernel(const float* __restrict__ w_out_i, const float* __restrict__ b_out_i,
              const float* __restrict__ w_out_d, const float* __restrict__ b_out_d,
              float* __restrict__ out) {
    constexpr int T = 1024;
    constexpr int CHUNK = NPGv / T;   // 4
    __shared__ unsigned skey[NPGv];
    __shared__ float    sval[NPGv];
    __shared__ int      hist[256];
    __shared__ int      s_sel, s_rem;
    __shared__ int      warp_sums[32];
    int tid  = threadIdx.x;
    int side = blockIdx.x >> 4;      // 0..1
    int b    = blockIdx.x & 15;      // 0..15
    int base = side * Nn + b * NPGv;
    int obase = (side * Bb + b) * Kk;
    float wo = side ? w_out_d[0] : w_out_i[0];
    float bo = side ? b_out_d[0] : b_out_i[0];

    if (tid < Cc) out[b * (2 * Cc) + side * Cc + tid] = 0.f;   // zero own out slice

    cudaGridDependencySynchronize();   // g_dn ready

    for (int j = tid; j < NPGv; j += T) {
        float2 dn = g_dn[base + j];
        float a   = (dn.y > 0.f) ? (dn.x / dn.y) : 0.f;   // empty segment -> 0
        float z   = a * wo + bo;
        float sc  = 0.5f * z * (1.f + erff(z * 0.70710678118654752f));  // exact gelu
        sval[j] = sc;
        skey[j] = encf(sc);
    }
    if (tid == 0) s_rem = Kk;

    // 4-pass radix select for the Kk-th largest key
    unsigned prefix = 0u;
#pragma unroll
    for (int shift = 24; shift >= 0; shift -= 8) {
        unsigned umask = (shift == 24) ? 0u : (0xFFFFFFFFu << (shift + 8));
        __syncthreads();
        if (tid < 256) hist[tid] = 0;
        __syncthreads();
#pragma unroll
        for (int u = 0; u < CHUNK; ++u) {
            unsigned key = skey[tid + u * T];
            bool act = (key & umask) == (prefix & umask);
            if (act) {
                unsigned bin   = (key >> shift) & 255u;
                unsigned peers = __match_any_sync(__activemask(), bin);
                int leader = __ffs(peers) - 1;
                if ((tid & 31) == leader) atomicAdd(&hist[bin], __popc(peers));
            }
        }
        __syncthreads();
        if (tid < 32) {
            int rem = s_rem;
            int h[8], sfx[8];
            int bin0 = tid * 8;
#pragma unroll
            for (int j = 0; j < 8; ++j) h[j] = hist[bin0 + j];
            sfx[7] = h[7];
#pragma unroll
            for (int j = 6; j >= 0; --j) sfx[j] = h[j] + sfx[j + 1];
            int tot = sfx[0];
            int suf = tot;
#pragma unroll
            for (int off = 1; off < 32; off <<= 1) {
                int v = __shfl_down_sync(0xFFFFFFFFu, suf, off);
                if (tid + off < 32) suf += v;
            }
            int above_lane = suf - tot;   // sum of bins >= (tid+1)*8
#pragma unroll
            for (int j = 0; j < 8; ++j) {
                int cnt_ge    = sfx[j] + above_lane;
                int cnt_above = (j == 7) ? above_lane : (sfx[j + 1] + above_lane);
                if (cnt_ge >= rem && cnt_above < rem) {
                    s_sel = bin0 + j;
                    s_rem = rem - cnt_above;
                }
            }
        }
        __syncthreads();
        prefix |= ((unsigned)s_sel) << shift;
    }
    unsigned thr = prefix;           // Kk-th largest key
    int need_eq = s_rem;             // #ties at thr to keep (lowest index first)

    int lane = tid & 31, warp = tid >> 5;
    auto excl_scan = [&](int cnt) -> int {
        int incl = cnt;
#pragma unroll
        for (int off = 1; off < 32; off <<= 1) {
            int v = __shfl_up_sync(0xFFFFFFFFu, incl, off);
            if (lane >= off) incl += v;
        }
        if (lane == 31) warp_sums[warp] = incl;
        __syncthreads();
        if (tid < 32) {
            int v = warp_sums[tid];
#pragma unroll
            for (int off = 1; off < 32; off <<= 1) {
                int t2 = __shfl_up_sync(0xFFFFFFFFu, v, off);
                if (tid >= off) v += t2;
            }
            warp_sums[tid] = v;
        }
        __syncthreads();
        return incl - cnt + (warp ? warp_sums[warp - 1] : 0);
    };

    // tie-rank scan (ascending index over keys == thr)
    int j0 = tid * CHUNK;
    int myties = 0;
#pragma unroll
    for (int u = 0; u < CHUNK; ++u) myties += (skey[j0 + u] == thr) ? 1 : 0;
    int r = excl_scan(myties);

    unsigned selmask = 0u;
    int nsel = 0;
#pragma unroll
    for (int u = 0; u < CHUNK; ++u) {
        unsigned key = skey[j0 + u];
        bool sel = key > thr;
        if (key == thr) { sel = (r < need_eq); ++r; }
        if (sel) { selmask |= (1u << u); ++nsel; }
    }
    __syncthreads();                 // warp_sums reuse
    int pos = excl_scan(nsel);

#pragma unroll
    for (int u = 0; u < CHUNK; ++u) {
        if (selmask & (1u << u)) {
            int j = j0 + u;
            g_sel[obase + pos]  = j;
            g_selw[obase + pos] = tanhf(sval[j]) * (1.f / (float)Kk);
            ++pos;
        }
    }
}

// ---- pooling: dense weighted sum over compacted top-K rows -----------------
__global__ void __launch_bounds__(256)
pool_kernel(const float* __restrict__ x_i, const float* __restrict__ x_d,
            float* __restrict__ out) {
    constexpr int RPB = Kk / PSPLIT;     // 64 rows per block
    __shared__ int   sidx[RPB];
    __shared__ float swt[RPB];
    int part = blockIdx.x & (PSPLIT - 1);
    int sb   = blockIdx.x >> 4;          // PSPLIT == 16
    int side = sb >> 4;
    int b    = sb & 15;
    const float* x = side ? x_d : x_i;
    int obase = (side * Bb + b) * Kk + part * RPB;
    long long xgbase = (long long)b * NPGv * Cc;

    cudaGridDependencySynchronize();     // g_sel/g_selw + out-zero ready

    if (threadIdx.x < RPB) {
        sidx[threadIdx.x] = g_sel[obase + threadIdx.x];
        swt[threadIdx.x]  = g_selw[obase + threadIdx.x];
    }
    __syncthreads();

    int cg = threadIdx.x & 63;           // float4 column group
    int rg = threadIdx.x >> 6;           // row group 0..3
    float4 acc = make_float4(0.f, 0.f, 0.f, 0.f);
#pragma unroll 16
    for (int r = rg; r < RPB; r += 4) {
        int   row = sidx[r];
        float w   = swt[r];
        float4 xv = __ldg(reinterpret_cast<const float4*>(x + xgbase + (long long)row * Cc + cg * 4));
        acc.x += w * xv.x; acc.y += w * xv.y;
        acc.z += w * xv.z; acc.w += w * xv.w;
    }
    float* o = &out[b * (2 * Cc) + side * Cc + cg * 4];
    atomicAdd(reinterpret_cast<float2*>(o),     make_float2(acc.x, acc.y));
    atomicAdd(reinterpret_cast<float2*>(o + 2), make_float2(acc.z, acc.w));
}

// ---- launch ----------------------------------------------------------------
extern "C" void kernel_launch(void* const* d_in, const int* in_sizes, int n_in,
                              void* d_out, int out_size) {
    const float* x_inst     = (const float*)d_in[0];
    const float* x_data     = (const float*)d_in[1];
    const float* w_kqv_inst = (const float*)d_in[2];
    const float* b_kqv_inst = (const float*)d_in[3];
    const float* w_kqv_data = (const float*)d_in[4];
    const float* b_kqv_data = (const float*)d_in[5];
    const float* w_out_inst = (const float*)d_in[6];
    const float* b_out_inst = (const float*)d_in[7];
    const float* w_out_data = (const float*)d_in[8];
    const float* b_out_data = (const float*)d_in[9];
    const float* krel_w     = (const float*)d_in[10];
    const float* krel_b     = (const float*)d_in[11];
    const float* vrel_w     = (const float*)d_in[12];
    const float* vrel_b     = (const float*)d_in[13];
    const float* p_rel      = (const float*)d_in[14];
    const int*   ei_i2d     = (const int*)d_in[15];
    const int*   ei_d2i     = (const int*)d_in[16];
    const int*   ei_i2i     = (const int*)d_in[17];
    float* out = (float*)d_out;

    kqv_kernel<<<(2 * Nn) / 64, 512>>>(x_inst, x_data, w_kqv_inst, b_kqv_inst,
                                       w_kqv_data, b_kqv_data);

    cudaLaunchAttribute attr[1];
    attr[0].id = cudaLaunchAttributeProgrammaticStreamSerialization;
    attr[0].val.programmaticStreamSerializationAllowed = 1;

    {
        cudaLaunchConfig_t cfg = {};
        cfg.gridDim  = dim3(3 * (Ee / 4096));
        cfg.blockDim = dim3(512);
        cfg.attrs = attr; cfg.numAttrs = 1;
        cudaLaunchKernelEx(&cfg, edge_kernel, ei_i2d, ei_d2i, ei_i2i,
                           krel_w, krel_b, vrel_w, vrel_b, p_rel);
    }
    {
        cudaLaunchConfig_t cfg = {};
        cfg.gridDim  = dim3(2 * Bb);
        cfg.blockDim = dim3(1024);
        cfg.attrs = attr; cfg.numAttrs = 1;
        cudaLaunchKernelEx(&cfg, select_kernel, w_out_inst, b_out_inst,
                           w_out_data, b_out_data, out);
    }
    {
        cudaLaunchConfig_t cfg = {};
        cfg.gridDim  = dim3(2 * Bb * PSPLIT);
        cfg.blockDim = dim3(256);
        cfg.attrs = attr; cfg.numAttrs = 1;
        cudaLaunchKernelEx(&cfg, pool_kernel, x_inst, x_data, out);
    }
}

// round 16
// speedup vs baseline: 1.0960x; 1.0834x over previous
#include <cuda_runtime.h>
#include <math.h>

// Problem constants (fixed shapes)
namespace {
constexpr int Nn   = 65536;    // B*NPG nodes per side
constexpr int Cc   = 256;      // feature dim
constexpr int Ee   = 1048576;  // edges per edge set
constexpr int Bb   = 16;       // batch
constexpr int NPGv = 4096;     // nodes per graph
constexpr int Kk   = 1024;     // top-k
constexpr int NT   = 131072;   // 2*N
constexpr int PSPLIT = 16;     // pooling splits per (side,batch): 64 rows each
constexpr int KQV_BLOCKS_PER_SIDE = 592;   // ~4 resident blocks/SM, grid-resident loop
constexpr int KQV_GROUPS = Nn / 32;        // 2048 groups of 32 nodes per side
}

// Scratch (device globals: no allocation allowed)
__device__ float2 g_kv[NT];    // (k, v) packed -> one gather sector
__device__ float  g_q[NT];     // compact q table (L1 evict_last gathers)
__device__ float2 g_dn[NT];    // (num, den) atomic accumulators
__device__ int    g_sel[2 * Bb * Kk];   // compacted selected row indices (local)
__device__ float  g_selw[2 * Bb * Kk];  // matching weights tanh(score)/K

// ---- float <-> order-preserving uint ------------------------------------
__device__ __forceinline__ unsigned encf(float f) {
    unsigned u = __float_as_uint(f);
    return (u & 0x80000000u) ? ~u : (u | 0x80000000u);
}

// q gather: pin in L1 (high reuse)
__device__ __forceinline__ float ldg_evict_last(const float* p) {
    float v;
    asm("ld.global.nc.L1::evict_last.f32 %0, [%1];" : "=f"(v) : "l"(p));
    return v;
}
// kv gather: don't displace the pinned q lines
__device__ __forceinline__ float2 ldg_kv_evict_first(const float2* p) {
    float2 v;
    asm("ld.global.nc.L1::evict_first.v2.f32 {%0, %1}, [%2];"
        : "=f"(v.x), "=f"(v.y) : "l"(p));
    return v;
}

// ---- kqv: grid-resident loop, 4 nodes per warp, 8 loads in flight ---------
// Streaming x (__ldcs) keeps g_kv/g_q/g_dn L2-resident for edge_kernel.
// Also zeroes g_dn.
__global__ void __launch_bounds__(256)
kqv_kernel(const float* __restrict__ x_i, const float* __restrict__ x_d,
           const float* __restrict__ w_i, const float* __restrict__ b_i,
           const float* __restrict__ w_d, const float* __restrict__ b_d) {
    __shared__ float4 sw0[Cc / 4], sw1[Cc / 4], sw2[Cc / 4];
    __shared__ float  sb[3];
    int side = blockIdx.x & 1;
    const float* w  = side ? w_d : w_i;
    const float* bb = side ? b_d : b_i;
    for (int c = threadIdx.x; c < Cc; c += blockDim.x) {
        reinterpret_cast<float*>(sw0)[c] = w[c * 3 + 0];
        reinterpret_cast<float*>(sw1)[c] = w[c * 3 + 1];
        reinterpret_cast<float*>(sw2)[c] = w[c * 3 + 2];
    }
    if (threadIdx.x < 3) sb[threadIdx.x] = bb[threadIdx.x];
    __syncthreads();

    int warp = threadIdx.x >> 5;     // 0..7
    int lane = threadIdx.x & 31;
    float4 rw0[2] = {sw0[lane], sw0[lane + 32]};
    float4 rw1[2] = {sw1[lane], sw1[lane + 32]};
    float4 rw2[2] = {sw2[lane], sw2[lane + 32]};
    float bk = sb[0], bq = sb[1], bv = sb[2];

    const float* xs = side ? x_d : x_i;
    int node_off = side * Nn;

    for (int g = (blockIdx.x >> 1); g < KQV_GROUPS; g += KQV_BLOCKS_PER_SIDE) {
        int local = g * 32 + warp * 4;                // 32 nodes per block-group
        const float* x = xs + (long long)local * Cc;

        // issue all 8 independent loads first (MLP=8)
        float4 xv[4][2];
#pragma unroll
        for (int n = 0; n < 4; ++n)
#pragma unroll
            for (int h = 0; h < 2; ++h)
                xv[n][h] = __ldcs(reinterpret_cast<const float4*>(
                    x + n * Cc + (lane + h * 32) * 4));

#pragma unroll
        for (int n = 0; n < 4; ++n) {
            float s0 = 0.f, s1 = 0.f, s2 = 0.f;
#pragma unroll
            for (int h = 0; h < 2; ++h) {
                float4 v  = xv[n][h];
                float4 w0 = rw0[h], w1 = rw1[h], w2 = rw2[h];
                s0 += v.x * w0.x + v.y * w0.y + v.z * w0.z + v.w * w0.w;
                s1 += v.x * w1.x + v.y * w1.y + v.z * w1.z + v.w * w1.w;
                s2 += v.x * w2.x + v.y * w2.y + v.z * w2.z + v.w * w2.w;
            }
#pragma unroll
            for (int o = 16; o; o >>= 1) {
                s0 += __shfl_down_sync(0xFFFFFFFFu, s0, o);
                s1 += __shfl_down_sync(0xFFFFFFFFu, s1, o);
                s2 += __shfl_down_sync(0xFFFFFFFFu, s2, o);
            }
            if (lane == 0) {
                int node = node_off + local + n;
                g_kv[node] = make_float2(s0 + bk, s2 + bv);   // (k, v)
                g_q[node]  = s1 + bq;
                g_dn[node] = make_float2(0.f, 0.f);
            }
        }
    }
}

// ---- single fused edge pass: 8 edges/thread, exp sums, no max-shift --------
// PDL: index loads (pure inputs) issue BEFORE the grid dependency sync.
__global__ void __launch_bounds__(512)
edge_kernel(const int* __restrict__ ei0, const int* __restrict__ ei1,
            const int* __restrict__ ei2,
            const float* __restrict__ krel_w, const float* __restrict__ krel_b,
            const float* __restrict__ vrel_w, const float* __restrict__ vrel_b,
            const float* __restrict__ p_rel) {
    int t  = blockIdx.x >> 8;                                  // 0,1,2 (uniform per block)
    int gi = ((blockIdx.x & 255) << 9) | threadIdx.x;          // 8-edge group, 0..Ee/8-1
    const int* ei = (t == 0) ? ei0 : ((t == 1) ? ei1 : ei2);
    const int4* sp = reinterpret_cast<const int4*>(ei) + gi * 2;
    const int4* dp = reinterpret_cast<const int4*>(ei + Ee) + gi * 2;
    int4 ss0 = __ldcs(sp), ss1 = __ldcs(sp + 1);
    int4 dd0 = __ldcs(dp), dd1 = __ldcs(dp + 1);
    float kw = krel_w[t], kb = krel_b[t];
    float vw = vrel_w[t], vb = vrel_b[t];
    float pr = p_rel[t];

    cudaGridDependencySynchronize();   // now g_kv/g_q/g_dn are ready

    int sbase = (t == 1) ? Nn : 0;
    int dbase = (t == 0) ? Nn : 0;
    int s[8] = {ss0.x, ss0.y, ss0.z, ss0.w, ss1.x, ss1.y, ss1.z, ss1.w};
    int d[8] = {dd0.x, dd0.y, dd0.z, dd0.w, dd1.x, dd1.y, dd1.z, dd1.w};
    float2 kv[8];
    float  q[8];
#pragma unroll
    for (int u = 0; u < 8; ++u) kv[u] = ldg_kv_evict_first(&g_kv[sbase + s[u]]);
#pragma unroll
    for (int u = 0; u < 8; ++u) q[u]  = ldg_evict_last(&g_q[dbase + d[u]]);
#pragma unroll
    for (int u = 0; u < 8; ++u) {
        float ex = __expf(q[u] * (kv[u].x * kw + kb) * pr);
        float ve = kv[u].y * vw + vb;
        atomicAdd(&g_dn[dbase + d[u]], make_float2(ex * ve, ex));
    }
}

// ---- score + per-batch top-K (radix select) + compaction -------------------
__global__ void __launch_bounds__(1024)
select_kernel(const float* __restrict__ w_out_i, const float* __restrict__ b_out_i,
              const float* __restrict__ w_out_d, const float* __restrict__ b_out_d,
              float* __restrict__ out) {
    constexpr int T = 1024;
    constexpr int CHUNK = NPGv / T;   // 4
    __shared__ unsigned skey[NPGv];
    __shared__ float    sval[NPGv];
    __shared__ int      hist[256];
    __shared__ int      s_sel, s_rem;
    __shared__ int      warp_sums[32];
    int tid  = threadIdx.x;
    int side = blockIdx.x >> 4;      // 0..1
    int b    = blockIdx.x & 15;      // 0..15
    int base = side * Nn + b * NPGv;
    int obase = (side * Bb + b) * Kk;
    float wo = side ? w_out_d[0] : w_out_i[0];
    float bo = side ? b_out_d[0] : b_out_i[0];

    if (tid < Cc) out[b * (2 * Cc) + side * Cc + tid] = 0.f;   // zero own out slice

    cudaGridDependencySynchronize();   // g_dn ready

    for (int j = tid; j < NPGv; j += T) {
        float2 dn = g_dn[base + j];
        float a   = (dn.y > 0.f) ? (dn.x / dn.y) : 0.f;   // empty segment -> 0
        float z   = a * wo + bo;
        float sc  = 0.5f * z * (1.f + erff(z * 0.70710678118654752f));  // exact gelu
        sval[j] = sc;
        skey[j] = encf(sc);
    }
    if (tid == 0) s_rem = Kk;

    // 4-pass radix select for the Kk-th largest key
    unsigned prefix = 0u;
#pragma unroll
    for (int shift = 24; shift >= 0; shift -= 8) {
        unsigned umask = (shift == 24) ? 0u : (0xFFFFFFFFu << (shift + 8));
        __syncthreads();
        if (tid < 256) hist[tid] = 0;
        __syncthreads();
#pragma unroll
        for (int u = 0; u < CHUNK; ++u) {
            unsigned key = skey[tid + u * T];
            bool act = (key & umask) == (prefix & umask);
            if (act) {
                unsigned bin   = (key >> shift) & 255u;
                unsigned peers = __match_any_sync(__activemask(), bin);
                int leader = __ffs(peers) - 1;
                if ((tid & 31) == leader) atomicAdd(&hist[bin], __popc(peers));
            }
        }
        __syncthreads();
        if (tid < 32) {
            int rem = s_rem;
            int h[8], sfx[8];
            int bin0 = tid * 8;
#pragma unroll
            for (int j = 0; j < 8; ++j) h[j] = hist[bin0 + j];
            sfx[7] = h[7];
#pragma unroll
            for (int j = 6; j >= 0; --j) sfx[j] = h[j] + sfx[j + 1];
            int tot = sfx[0];
            int suf = tot;
#pragma unroll
            for (int off = 1; off < 32; off <<= 1) {
                int v = __shfl_down_sync(0xFFFFFFFFu, suf, off);
                if (tid + off < 32) suf += v;
            }
            int above_lane = suf - tot;   // sum of bins >= (tid+1)*8
#pragma unroll
            for (int j = 0; j < 8; ++j) {
                int cnt_ge    = sfx[j] + above_lane;
                int cnt_above = (j == 7) ? above_lane : (sfx[j + 1] + above_lane);
                if (cnt_ge >= rem && cnt_above < rem) {
                    s_sel = bin0 + j;
                    s_rem = rem - cnt_above;
                }
            }
        }
        __syncthreads();
        prefix |= ((unsigned)s_sel) << shift;
    }
    unsigned thr = prefix;           // Kk-th largest key
    int need_eq = s_rem;             // #ties at thr to keep (lowest index first)

    int lane = tid & 31, warp = tid >> 5;
    auto excl_scan = [&](int cnt) -> int {
        int incl = cnt;
#pragma unroll
        for (int off = 1; off < 32; off <<= 1) {
            int v = __shfl_up_sync(0xFFFFFFFFu, incl, off);
            if (lane >= off) incl += v;
        }
        if (lane == 31) warp_sums[warp] = incl;
        __syncthreads();
        if (tid < 32) {
            int v = warp_sums[tid];
#pragma unroll
            for (int off = 1; off < 32; off <<= 1) {
                int t2 = __shfl_up_sync(0xFFFFFFFFu, v, off);
                if (tid >= off) v += t2;
            }
            warp_sums[tid] = v;
        }
        __syncthreads();
        return incl - cnt + (warp ? warp_sums[warp - 1] : 0);
    };

    // tie-rank scan (ascending index over keys == thr)
    int j0 = tid * CHUNK;
    int myties = 0;
#pragma unroll
    for (int u = 0; u < CHUNK; ++u) myties += (skey[j0 + u] == thr) ? 1 : 0;
    int r = excl_scan(myties);

    unsigned selmask = 0u;
    int nsel = 0;
#pragma unroll
    for (int u = 0; u < CHUNK; ++u) {
        unsigned key = skey[j0 + u];
        bool sel = key > thr;
        if (key == thr) { sel = (r < need_eq); ++r; }
        if (sel) { selmask |= (1u << u); ++nsel; }
    }
    __syncthreads();                 // warp_sums reuse
    int pos = excl_scan(nsel);

#pragma unroll
    for (int u = 0; u < CHUNK; ++u) {
        if (selmask & (1u << u)) {
            int j = j0 + u;
            g_sel[obase + pos]  = j;
            g_selw[obase + pos] = tanhf(sval[j]) * (1.f / (float)Kk);
            ++pos;
        }
    }
}

// ---- pooling: dense weighted sum over compacted top-K rows -----------------
__global__ void __launch_bounds__(256)
pool_kernel(const float* __restrict__ x_i, const float* __restrict__ x_d,
            float* __restrict__ out) {
    constexpr int RPB = Kk / PSPLIT;     // 64 rows per block
    __shared__ int   sidx[RPB];
    __shared__ float swt[RPB];
    int part = blockIdx.x & (PSPLIT - 1);
    int sb   = blockIdx.x >> 4;          // PSPLIT == 16
    int side = sb >> 4;
    int b    = sb & 15;
    const float* x = side ? x_d : x_i;
    int obase = (side * Bb + b) * Kk + part * RPB;
    long long xgbase = (long long)b * NPGv * Cc;

    cudaGridDependencySynchronize();     // g_sel/g_selw + out-zero ready

    if (threadIdx.x < RPB) {
        sidx[threadIdx.x] = g_sel[obase + threadIdx.x];
        swt[threadIdx.x]  = g_selw[obase + threadIdx.x];
    }
    __syncthreads();

    int cg = threadIdx.x & 63;           // float4 column group
    int rg = threadIdx.x >> 6;           // row group 0..3
    float4 acc = make_float4(0.f, 0.f, 0.f, 0.f);
#pragma unroll 16
    for (int r = rg; r < RPB; r += 4) {
        int   row = sidx[r];
        float w   = swt[r];
        float4 xv = __ldg(reinterpret_cast<const float4*>(x + xgbase + (long long)row * Cc + cg * 4));
        acc.x += w * xv.x; acc.y += w * xv.y;
        acc.z += w * xv.z; acc.w += w * xv.w;
    }
    float* o = &out[b * (2 * Cc) + side * Cc + cg * 4];
    atomicAdd(reinterpret_cast<float2*>(o),     make_float2(acc.x, acc.y));
    atomicAdd(reinterpret_cast<float2*>(o + 2), make_float2(acc.z, acc.w));
}

// ---- launch ----------------------------------------------------------------
extern "C" void kernel_launch(void* const* d_in, const int* in_sizes, int n_in,
                              void* d_out, int out_size) {
    const float* x_inst     = (const float*)d_in[0];
    const float* x_data     = (const float*)d_in[1];
    const float* w_kqv_inst = (const float*)d_in[2];
    const float* b_kqv_inst = (const float*)d_in[3];
    const float* w_kqv_data = (const float*)d_in[4];
    const float* b_kqv_data = (const float*)d_in[5];
    const float* w_out_inst = (const float*)d_in[6];
    const float* b_out_inst = (const float*)d_in[7];
    const float* w_out_data = (const float*)d_in[8];
    const float* b_out_data = (const float*)d_in[9];
    const float* krel_w     = (const float*)d_in[10];
    const float* krel_b     = (const float*)d_in[11];
    const float* vrel_w     = (const float*)d_in[12];
    const float* vrel_b     = (const float*)d_in[13];
    const float* p_rel      = (const float*)d_in[14];
    const int*   ei_i2d     = (const int*)d_in[15];
    const int*   ei_d2i     = (const int*)d_in[16];
    const int*   ei_i2i     = (const int*)d_in[17];
    float* out = (float*)d_out;

    kqv_kernel<<<2 * KQV_BLOCKS_PER_SIDE, 256>>>(x_inst, x_data, w_kqv_inst, b_kqv_inst,
                                                 w_kqv_data, b_kqv_data);

    cudaLaunchAttribute attr[1];
    attr[0].id = cudaLaunchAttributeProgrammaticStreamSerialization;
    attr[0].val.programmaticStreamSerializationAllowed = 1;

    {
        cudaLaunchConfig_t cfg = {};
        cfg.gridDim  = dim3(3 * (Ee / 4096));
        cfg.blockDim = dim3(512);
        cfg.attrs = attr; cfg.numAttrs = 1;
        cudaLaunchKernelEx(&cfg, edge_kernel, ei_i2d, ei_d2i, ei_i2i,
                           krel_w, krel_b, vrel_w, vrel_b, p_rel);
    }
    {
        cudaLaunchConfig_t cfg = {};
        cfg.gridDim  = dim3(2 * Bb);
        cfg.blockDim = dim3(1024);
        cfg.attrs = attr; cfg.numAttrs = 1;
        cudaLaunchKernelEx(&cfg, select_kernel, w_out_inst, b_out_inst,
                           w_out_data, b_out_data, out);
    }
    {
        cudaLaunchConfig_t cfg = {};
        cfg.gridDim  = dim3(2 * Bb * PSPLIT);
        cfg.blockDim = dim3(256);
        cfg.attrs = attr; cfg.numAttrs = 1;
        cudaLaunchKernelEx(&cfg, pool_kernel, x_inst, x_data, out);
    }
}

// round 17
// speedup vs baseline: 1.1272x; 1.0285x over previous
#include <cuda_runtime.h>
#include <math.h>

// Problem constants (fixed shapes)
namespace {
constexpr int Nn   = 65536;    // B*NPG nodes per side
constexpr int Cc   = 256;      // feature dim
constexpr int Ee   = 1048576;  // edges per edge set
constexpr int Bb   = 16;       // batch
constexpr int NPGv = 4096;     // nodes per graph
constexpr int Kk   = 1024;     // top-k
constexpr int NT   = 131072;   // 2*N
constexpr int PSPLIT = 16;     // pooling splits per (side,batch): 64 rows each
constexpr int KQV_BLOCKS_PER_SIDE = 592;   // ~4 resident blocks/SM, grid-resident loop
constexpr int KQV_GROUPS = Nn / 32;        // 2048 groups of 32 nodes per side
}

// Scratch (device globals: no allocation allowed)
__device__ float2 g_kv[NT];    // (k, v) packed -> one gather sector
__device__ float  g_q[NT];     // compact q table (L1 evict_last gathers)
__device__ float2 g_dn[NT];    // (num, den) atomic accumulators
__device__ int    g_sel[2 * Bb * Kk];   // compacted selected row indices (local)
__device__ float  g_selw[2 * Bb * Kk];  // matching weights tanh(score)/K

// ---- float <-> order-preserving uint ------------------------------------
__device__ __forceinline__ unsigned encf(float f) {
    unsigned u = __float_as_uint(f);
    return (u & 0x80000000u) ? ~u : (u | 0x80000000u);
}

// q gather: pin in L1 (high reuse)
__device__ __forceinline__ float ldg_evict_last(const float* p) {
    float v;
    asm("ld.global.nc.L1::evict_last.f32 %0, [%1];" : "=f"(v) : "l"(p));
    return v;
}
// kv gather: don't displace the pinned q lines
__device__ __forceinline__ float2 ldg_kv_evict_first(const float2* p) {
    float2 v;
    asm("ld.global.nc.L1::evict_first.v2.f32 {%0, %1}, [%2];"
        : "=f"(v.x), "=f"(v.y) : "l"(p));
    return v;
}

// ---- kqv: grid-resident loop, 4 nodes per warp, 8 loads in flight ---------
// Streaming x (__ldcs) keeps g_kv/g_q/g_dn L2-resident for edge_kernel.
// Also zeroes g_dn.
__global__ void __launch_bounds__(256)
kqv_kernel(const float* __restrict__ x_i, const float* __restrict__ x_d,
           const float* __restrict__ w_i, const float* __restrict__ b_i,
           const float* __restrict__ w_d, const float* __restrict__ b_d) {
    __shared__ float4 sw0[Cc / 4], sw1[Cc / 4], sw2[Cc / 4];
    __shared__ float  sb[3];
    int side = blockIdx.x & 1;
    const float* w  = side ? w_d : w_i;
    const float* bb = side ? b_d : b_i;
    for (int c = threadIdx.x; c < Cc; c += blockDim.x) {
        reinterpret_cast<float*>(sw0)[c] = w[c * 3 + 0];
        reinterpret_cast<float*>(sw1)[c] = w[c * 3 + 1];
        reinterpret_cast<float*>(sw2)[c] = w[c * 3 + 2];
    }
    if (threadIdx.x < 3) sb[threadIdx.x] = bb[threadIdx.x];
    __syncthreads();

    int warp = threadIdx.x >> 5;     // 0..7
    int lane = threadIdx.x & 31;
    float4 rw0[2] = {sw0[lane], sw0[lane + 32]};
    float4 rw1[2] = {sw1[lane], sw1[lane + 32]};
    float4 rw2[2] = {sw2[lane], sw2[lane + 32]};
    float bk = sb[0], bq = sb[1], bv = sb[2];

    const float* xs = side ? x_d : x_i;
    int node_off = side * Nn;

    for (int g = (blockIdx.x >> 1); g < KQV_GROUPS; g += KQV_BLOCKS_PER_SIDE) {
        int local = g * 32 + warp * 4;                // 32 nodes per block-group
        const float* x = xs + (long long)local * Cc;

        // issue all 8 independent loads first (MLP=8)
        float4 xv[4][2];
#pragma unroll
        for (int n = 0; n < 4; ++n)
#pragma unroll
            for (int h = 0; h < 2; ++h)
                xv[n][h] = __ldcs(reinterpret_cast<const float4*>(
                    x + n * Cc + (lane + h * 32) * 4));

#pragma unroll
        for (int n = 0; n < 4; ++n) {
            float s0 = 0.f, s1 = 0.f, s2 = 0.f;
#pragma unroll
            for (int h = 0; h < 2; ++h) {
                float4 v  = xv[n][h];
                float4 w0 = rw0[h], w1 = rw1[h], w2 = rw2[h];
                s0 += v.x * w0.x + v.y * w0.y + v.z * w0.z + v.w * w0.w;
                s1 += v.x * w1.x + v.y * w1.y + v.z * w1.z + v.w * w1.w;
                s2 += v.x * w2.x + v.y * w2.y + v.z * w2.z + v.w * w2.w;
            }
#pragma unroll
            for (int o = 16; o; o >>= 1) {
                s0 += __shfl_down_sync(0xFFFFFFFFu, s0, o);
                s1 += __shfl_down_sync(0xFFFFFFFFu, s1, o);
                s2 += __shfl_down_sync(0xFFFFFFFFu, s2, o);
            }
            if (lane == 0) {
                int node = node_off + local + n;
                g_kv[node] = make_float2(s0 + bk, s2 + bv);   // (k, v)
                g_q[node]  = s1 + bq;
                g_dn[node] = make_float2(0.f, 0.f);
            }
        }
    }
}

// ---- single fused edge pass: 8 edges/thread, exp sums, no max-shift --------
// PDL: index loads (pure inputs) issue BEFORE the grid dependency sync.
__global__ void __launch_bounds__(512)
edge_kernel(const int* __restrict__ ei0, const int* __restrict__ ei1,
            const int* __restrict__ ei2,
            const float* __restrict__ krel_w, const float* __restrict__ krel_b,
            const float* __restrict__ vrel_w, const float* __restrict__ vrel_b,
            const float* __restrict__ p_rel) {
    int t  = blockIdx.x >> 8;                                  // 0,1,2 (uniform per block)
    int gi = ((blockIdx.x & 255) << 9) | threadIdx.x;          // 8-edge group, 0..Ee/8-1
    const int* ei = (t == 0) ? ei0 : ((t == 1) ? ei1 : ei2);
    const int4* sp = reinterpret_cast<const int4*>(ei) + gi * 2;
    const int4* dp = reinterpret_cast<const int4*>(ei + Ee) + gi * 2;
    int4 ss0 = __ldcs(sp), ss1 = __ldcs(sp + 1);
    int4 dd0 = __ldcs(dp), dd1 = __ldcs(dp + 1);
    float kw = krel_w[t], kb = krel_b[t];
    float vw = vrel_w[t], vb = vrel_b[t];
    float pr = p_rel[t];

    cudaGridDependencySynchronize();   // now g_kv/g_q/g_dn are ready

    int sbase = (t == 1) ? Nn : 0;
    int dbase = (t == 0) ? Nn : 0;
    int s[8] = {ss0.x, ss0.y, ss0.z, ss0.w, ss1.x, ss1.y, ss1.z, ss1.w};
    int d[8] = {dd0.x, dd0.y, dd0.z, dd0.w, dd1.x, dd1.y, dd1.z, dd1.w};
    float2 kv[8];
    float  q[8];
#pragma unroll
    for (int u = 0; u < 8; ++u) kv[u] = ldg_kv_evict_first(&g_kv[sbase + s[u]]);
#pragma unroll
    for (int u = 0; u < 8; ++u) q[u]  = ldg_evict_last(&g_q[dbase + d[u]]);
#pragma unroll
    for (int u = 0; u < 8; ++u) {
        float ex = __expf(q[u] * (kv[u].x * kw + kb) * pr);
        float ve = kv[u].y * vw + vb;
        atomicAdd(&g_dn[dbase + d[u]], make_float2(ex * ve, ex));
    }
}

// ---- score + per-batch top-K (radix select) + compaction -------------------
__global__ void __launch_bounds__(1024)
select_kernel(const float* __restrict__ w_out_i, const float* __restrict__ b_out_i,
              const float* __restrict__ w_out_d, const float* __restrict__ b_out_d,
              float* __restrict__ out) {
    constexpr int T = 1024;
    constexpr int CHUNK = NPGv / T;   // 4
    __shared__ unsigned skey[NPGv];
    __shared__ float    sval[NPGv];
    __shared__ int      hist[256];
    __shared__ int      s_sel, s_rem;
    __shared__ int      warp_sums[32];
    int tid  = threadIdx.x;
    int side = blockIdx.x >> 4;      // 0..1
    int b    = blockIdx.x & 15;      // 0..15
    int base = side * Nn + b * NPGv;
    int obase = (side * Bb + b) * Kk;
    float wo = side ? w_out_d[0] : w_out_i[0];
    float bo = side ? b_out_d[0] : b_out_i[0];

    if (tid < Cc) out[b * (2 * Cc) + side * Cc + tid] = 0.f;   // zero own out slice

    cudaGridDependencySynchronize();   // g_dn ready

    for (int j = tid; j < NPGv; j += T) {
        float2 dn = g_dn[base + j];
        float a   = (dn.y > 0.f) ? (dn.x / dn.y) : 0.f;   // empty segment -> 0
        float z   = a * wo + bo;
        float sc  = 0.5f * z * (1.f + erff(z * 0.70710678118654752f));  // exact gelu
        sval[j] = sc;
        skey[j] = encf(sc);
    }
    if (tid == 0) s_rem = Kk;

    // 4-pass radix select for the Kk-th largest key
    unsigned prefix = 0u;
#pragma unroll
    for (int shift = 24; shift >= 0; shift -= 8) {
        unsigned umask = (shift == 24) ? 0u : (0xFFFFFFFFu << (shift + 8));
        __syncthreads();
        if (tid < 256) hist[tid] = 0;
        __syncthreads();
#pragma unroll
        for (int u = 0; u < CHUNK; ++u) {
            unsigned key = skey[tid + u * T];
            bool act = (key & umask) == (prefix & umask);
            if (act) {
                unsigned bin   = (key >> shift) & 255u;
                unsigned peers = __match_any_sync(__activemask(), bin);
                int leader = __ffs(peers) - 1;
                if ((tid & 31) == leader) atomicAdd(&hist[bin], __popc(peers));
            }
        }
        __syncthreads();
        if (tid < 32) {
            int rem = s_rem;
            int h[8], sfx[8];
            int bin0 = tid * 8;
#pragma unroll
            for (int j = 0; j < 8; ++j) h[j] = hist[bin0 + j];
            sfx[7] = h[7];
#pragma unroll
            for (int j = 6; j >= 0; --j) sfx[j] = h[j] + sfx[j + 1];
            int tot = sfx[0];
            int suf = tot;
#pragma unroll
            for (int off = 1; off < 32; off <<= 1) {
                int v = __shfl_down_sync(0xFFFFFFFFu, suf, off);
                if (tid + off < 32) suf += v;
            }
            int above_lane = suf - tot;   // sum of bins >= (tid+1)*8
#pragma unroll
            for (int j = 0; j < 8; ++j) {
                int cnt_ge    = sfx[j] + above_lane;
                int cnt_above = (j == 7) ? above_lane : (sfx[j + 1] + above_lane);
                if (cnt_ge >= rem && cnt_above < rem) {
                    s_sel = bin0 + j;
                    s_rem = rem - cnt_above;
                }
            }
        }
        __syncthreads();
        prefix |= ((unsigned)s_sel) << shift;
    }
    unsigned thr = prefix;           // Kk-th largest key
    int need_eq = s_rem;             // #ties at thr to keep (lowest index first)

    int lane = tid & 31, warp = tid >> 5;
    auto excl_scan = [&](int cnt) -> int {
        int incl = cnt;
#pragma unroll
        for (int off = 1; off < 32; off <<= 1) {
            int v = __shfl_up_sync(0xFFFFFFFFu, incl, off);
            if (lane >= off) incl += v;
        }
        if (lane == 31) warp_sums[warp] = incl;
        __syncthreads();
        if (tid < 32) {
            int v = warp_sums[tid];
#pragma unroll
            for (int off = 1; off < 32; off <<= 1) {
                int t2 = __shfl_up_sync(0xFFFFFFFFu, v, off);
                if (tid >= off) v += t2;
            }
            warp_sums[tid] = v;
        }
        __syncthreads();
        return incl - cnt + (warp ? warp_sums[warp - 1] : 0);
    };

    // tie-rank scan (ascending index over keys == thr)
    int j0 = tid * CHUNK;
    int myties = 0;
#pragma unroll
    for (int u = 0; u < CHUNK; ++u) myties += (skey[j0 + u] == thr) ? 1 : 0;
    int r = excl_scan(myties);

    unsigned selmask = 0u;
    int nsel = 0;
#pragma unroll
    for (int u = 0; u < CHUNK; ++u) {
        unsigned key = skey[j0 + u];
        bool sel = key > thr;
        if (key == thr) { sel = (r < need_eq); ++r; }
        if (sel) { selmask |= (1u << u); ++nsel; }
    }
    __syncthreads();                 // warp_sums reuse
    int pos = excl_scan(nsel);

#pragma unroll
    for (int u = 0; u < CHUNK; ++u) {
        if (selmask & (1u << u)) {
            int j = j0 + u;
            g_sel[obase + pos]  = j;
            g_selw[obase + pos] = tanhf(sval[j]) * (1.f / (float)Kk);
            ++pos;
        }
    }
}

// ---- pooling: dense weighted sum, 512 threads (8 row groups), smem reduce --
__global__ void __launch_bounds__(512)
pool_kernel(const float* __restrict__ x_i, const float* __restrict__ x_d,
            float* __restrict__ out) {
    constexpr int RPB = Kk / PSPLIT;     // 64 rows per block
    __shared__ int    sidx[RPB];
    __shared__ float  swt[RPB];
    __shared__ float4 sacc[8][64];       // 8 row-groups x 64 col-groups
    int part = blockIdx.x & (PSPLIT - 1);
    int sb   = blockIdx.x >> 4;          // PSPLIT == 16
    int side = sb >> 4;
    int b    = sb & 15;
    const float* x = side ? x_d : x_i;
    int obase = (side * Bb + b) * Kk + part * RPB;
    long long xgbase = (long long)b * NPGv * Cc;

    cudaGridDependencySynchronize();     // g_sel/g_selw + out-zero ready

    if (threadIdx.x < RPB) {
        sidx[threadIdx.x] = g_sel[obase + threadIdx.x];
        swt[threadIdx.x]  = g_selw[obase + threadIdx.x];
    }
    __syncthreads();

    int cg = threadIdx.x & 63;           // float4 column group
    int rg = threadIdx.x >> 6;           // row group 0..7
    float4 acc = make_float4(0.f, 0.f, 0.f, 0.f);
#pragma unroll 8
    for (int r = rg; r < RPB; r += 8) {
        int   row = sidx[r];
        float w   = swt[r];
        float4 xv = __ldg(reinterpret_cast<const float4*>(x + xgbase + (long long)row * Cc + cg * 4));
        acc.x += w * xv.x; acc.y += w * xv.y;
        acc.z += w * xv.z; acc.w += w * xv.w;
    }
    sacc[rg][cg] = acc;
    __syncthreads();
    if (threadIdx.x < 64) {
        float4 sum = sacc[0][threadIdx.x];
#pragma unroll
        for (int g = 1; g < 8; ++g) {
            float4 v = sacc[g][threadIdx.x];
            sum.x += v.x; sum.y += v.y; sum.z += v.z; sum.w += v.w;
        }
        float* o = &out[b * (2 * Cc) + side * Cc + threadIdx.x * 4];
        atomicAdd(reinterpret_cast<float2*>(o),     make_float2(sum.x, sum.y));
        atomicAdd(reinterpret_cast<float2*>(o + 2), make_float2(sum.z, sum.w));
    }
}

// ---- launch ----------------------------------------------------------------
extern "C" void kernel_launch(void* const* d_in, const int* in_sizes, int n_in,
                              void* d_out, int out_size) {
    const float* x_inst     = (const float*)d_in[0];
    const float* x_data     = (const float*)d_in[1];
    const float* w_kqv_inst = (const float*)d_in[2];
    const float* b_kqv_inst = (const float*)d_in[3];
    const float* w_kqv_data = (const float*)d_in[4];
    const float* b_kqv_data = (const float*)d_in[5];
    const float* w_out_inst = (const float*)d_in[6];
    const float* b_out_inst = (const float*)d_in[7];
    const float* w_out_data = (const float*)d_in[8];
    const float* b_out_data = (const float*)d_in[9];
    const float* krel_w     = (const float*)d_in[10];
    const float* krel_b     = (const float*)d_in[11];
    const float* vrel_w     = (const float*)d_in[12];
    const float* vrel_b     = (const float*)d_in[13];
    const float* p_rel      = (const float*)d_in[14];
    const int*   ei_i2d     = (const int*)d_in[15];
    const int*   ei_d2i     = (const int*)d_in[16];
    const int*   ei_i2i     = (const int*)d_in[17];
    float* out = (float*)d_out;

    kqv_kernel<<<2 * KQV_BLOCKS_PER_SIDE, 256>>>(x_inst, x_data, w_kqv_inst, b_kqv_inst,
                                                 w_kqv_data, b_kqv_data);

    cudaLaunchAttribute attr[1];
    attr[0].id = cudaLaunchAttributeProgrammaticStreamSerialization;
    attr[0].val.programmaticStreamSerializationAllowed = 1;

    {
        cudaLaunchConfig_t cfg = {};
        cfg.gridDim  = dim3(3 * (Ee / 4096));
        cfg.blockDim = dim3(512);
        cfg.attrs = attr; cfg.numAttrs = 1;
        cudaLaunchKernelEx(&cfg, edge_kernel, ei_i2d, ei_d2i, ei_i2i,
                           krel_w, krel_b, vrel_w, vrel_b, p_rel);
    }
    {
        cudaLaunchConfig_t cfg = {};
        cfg.gridDim  = dim3(2 * Bb);
        cfg.blockDim = dim3(1024);
        cfg.attrs = attr; cfg.numAttrs = 1;
        cudaLaunchKernelEx(&cfg, select_kernel, w_out_inst, b_out_inst,
                           w_out_data, b_out_data, out);
    }
    {
        cudaLaunchConfig_t cfg = {};
        cfg.gridDim  = dim3(2 * Bb * PSPLIT);
        cfg.blockDim = dim3(512);
        cfg.attrs = attr; cfg.numAttrs = 1;
        cudaLaunchKernelEx(&cfg, pool_kernel, x_inst, x_data, out);
    }
}